// round 8
// baseline (speedup 1.0000x reference)
#include <cuda_runtime.h>
#include <cstdint>

// Problem constants (B=64, C=512, H=W=28, G=8)
#define HWN    784       // H*W
#define HW4    196       // HW/4
#define CPG    64        // channels per group
#define CSZ    4         // cluster size
#define CPC    16        // channels per CTA (quarter group)
#define NCTA   2048      // 512 tiles x 4 CTAs
#define EPS    1e-5f
#define NTHR   256       // 8 warps

#define PART_BYTES  (CPC * HWN * 4)     // 50176
#define CHUNK_BYTES (PART_BYTES / 2)    // 25088

// smem layout (floats):
//   [0, CPC*HWN)   x quarter-tile (12544 floats)
//   + HWN          s partial / gate (784, float4-viewed)
//   + CPC          channel means (16)
//   + 20           reduction scratch (16 partials + mu + rsig)
//   + 2            mbarrier (u64, 8B aligned)
#define OFF_S     (CPC * HWN)
#define OFF_MEANS (OFF_S + HWN)
#define OFF_RED   (OFF_MEANS + CPC)
#define OFF_MBAR  (OFF_RED + 20)
#define SMEM_FLOATS (OFF_MBAR + 2)
#define SMEM_BYTES  (SMEM_FLOATS * 4)   // ~53.5 KB -> 4 CTAs/SM

__device__ __forceinline__ uint32_t smem_u32(const void* p) {
    uint32_t a;
    asm("{ .reg .u64 t; cvta.to.shared.u64 t, %1; cvt.u32.u64 %0, t; }"
        : "=r"(a) : "l"(p));
    return a;
}

__device__ __forceinline__ void cluster_sync_() {
    asm volatile("barrier.cluster.arrive.aligned;" ::: "memory");
    asm volatile("barrier.cluster.wait.aligned;" ::: "memory");
}

__global__ __launch_bounds__(NTHR, 4) __cluster_dims__(CSZ, 1, 1)
void simam_cluster4_kernel(const float* __restrict__ x,
                           const float* __restrict__ weight,
                           const float* __restrict__ bias,
                           float* __restrict__ out)
{
    extern __shared__ float smem[];
    float*  sx      = smem;
    float4* s_s4    = (float4*)(smem + OFF_S);      // 196 float4 partial s / gate
    float*  s_means = smem + OFF_MEANS;
    float*  s_red   = smem + OFF_RED;
    const uint32_t mbar = smem_u32(smem + OFF_MBAR);

    const int rank = (int)(blockIdx.x & (CSZ - 1));
    const int bg   = (int)(blockIdx.x >> 2);
    const int g    = bg & 7;
    const float* xt = x   + (size_t)bg * (CPG * HWN) + (size_t)rank * (CPC * HWN);
    float*       ot = out + (size_t)bg * (CPG * HWN) + (size_t)rank * (CPC * HWN);

    const int tid  = threadIdx.x;
    const int w    = tid >> 5;
    const int lane = tid & 31;

    // ---- TMA bulk load of this CTA's 16-channel slice (contiguous 50 KB) ----
    if (tid == 0) {
        asm volatile("mbarrier.init.shared::cta.b64 [%0], 1;" :: "r"(mbar) : "memory");
    }
    __syncthreads();
    if (tid == 0) {
        asm volatile("mbarrier.arrive.expect_tx.shared::cta.b64 _, [%0], %1;"
                     :: "r"(mbar), "r"((uint32_t)PART_BYTES) : "memory");
        const uint32_t dst0 = smem_u32(sx);
        #pragma unroll
        for (int i = 0; i < 2; i++) {
            asm volatile(
                "cp.async.bulk.shared::cluster.global.mbarrier::complete_tx::bytes "
                "[%0], [%1], %2, [%3];"
                :: "r"(dst0 + i * CHUNK_BYTES),
                   "l"((const char*)xt + i * CHUNK_BYTES),
                   "r"((uint32_t)CHUNK_BYTES),
                   "r"(mbar)
                : "memory");
        }
    }
    asm volatile(
        "{\n\t"
        ".reg .pred P;\n\t"
        "WL_%=: mbarrier.try_wait.parity.acquire.cta.shared::cta.b64 P, [%0], 0, 0x989680;\n\t"
        "@P bra WD_%=;\n\t"
        "bra WL_%=;\n\t"
        "WD_%=:\n\t"
        "}" :: "r"(mbar) : "memory");

    // ---- per-channel means: 8 warps x 2 channels ----
    #pragma unroll
    for (int i = 0; i < 2; i++) {
        const int c = w + 8 * i;
        const float4* row = (const float4*)(sx + c * HWN);
        float cs = 0.f;
        #pragma unroll
        for (int k = 0; k < 7; k++) {
            const int j = lane + 32 * k;
            if (j < HW4) {
                float4 v = row[j];
                cs += (v.x + v.y) + (v.z + v.w);
            }
        }
        #pragma unroll
        for (int o = 16; o; o >>= 1) cs += __shfl_xor_sync(0xffffffffu, cs, o);
        if (lane == 0) s_means[c] = cs * (1.0f / HWN);
    }
    __syncthreads();

    // ---- partial s over this CTA's 16 channels ----
    float4 acc = make_float4(0.f, 0.f, 0.f, 0.f);
    if (tid < HW4) {
        const float4* col = (const float4*)sx + tid;    // stride HW4 per channel
        #pragma unroll
        for (int c = 0; c < CPC; c++) {
            const float  m = s_means[c];
            const float4 v = col[c * HW4];
            acc.x += m * v.x;
            acc.y += m * v.y;
            acc.z += m * v.z;
            acc.w += m * v.w;
        }
        s_s4[tid] = acc;       // publish partial for peers
    }
    // all CTAs must have published partials before cross-reads
    cluster_sync_();

    // ---- fetch 3 peer partials via DSMEM, form total s in registers ----
    float4 tot = acc;
    if (tid < HW4) {
        const uint32_t laddr = smem_u32(&s_s4[tid]);
        #pragma unroll
        for (int d = 1; d < CSZ; d++) {
            const int pr = rank ^ d;     // visit every peer exactly once
            uint32_t raddr;
            asm("mapa.shared::cluster.u32 %0, %1, %2;"
                : "=r"(raddr) : "r"(laddr), "r"(pr));
            float4 p;
            asm volatile("ld.shared::cluster.v4.f32 {%0,%1,%2,%3}, [%4];"
                         : "=f"(p.x), "=f"(p.y), "=f"(p.z), "=f"(p.w)
                         : "r"(raddr));
            tot.x += p.x; tot.y += p.y; tot.z += p.z; tot.w += p.w;
        }
    }

    // ---- stats over total s (redundant in all CTAs, deterministic) ----
    float lsum = 0.f, lsq = 0.f;
    if (tid < HW4) {
        lsum = (tot.x + tot.y) + (tot.z + tot.w);
        lsq  = tot.x * tot.x + tot.y * tot.y + tot.z * tot.z + tot.w * tot.w;
    }
    #pragma unroll
    for (int o = 16; o; o >>= 1) {
        lsum += __shfl_xor_sync(0xffffffffu, lsum, o);
        lsq  += __shfl_xor_sync(0xffffffffu, lsq,  o);
    }
    if (lane == 0) { s_red[w] = lsum; s_red[8 + w] = lsq; }
    __syncthreads();
    if (tid == 0) {
        float ts = 0.f, tq = 0.f;
        #pragma unroll
        for (int i = 0; i < 8; i++) { ts += s_red[i]; tq += s_red[8 + i]; }
        const float mu  = ts * (1.0f / HWN);
        const float var = tq * (1.0f / HWN) - mu * mu;
        s_red[16] = mu;
        s_red[17] = rsqrtf(var + EPS);
    }
    // peers must finish reading our partial s before we overwrite it with gate
    cluster_sync_();

    // ---- gate written into s buffer ----
    {
        const float mu = s_red[16];
        const float rs = s_red[17];
        const float wg = weight[g];
        const float bb = bias[g];
        if (tid < HW4) {
            float4 gt;
            gt.x = 1.0f / (1.0f + __expf(-((tot.x - mu) * rs * wg + bb)));
            gt.y = 1.0f / (1.0f + __expf(-((tot.y - mu) * rs * wg + bb)));
            gt.z = 1.0f / (1.0f + __expf(-((tot.z - mu) * rs * wg + bb)));
            gt.w = 1.0f / (1.0f + __expf(-((tot.w - mu) * rs * wg + bb)));
            s_s4[tid] = gt;
        }
    }
    __syncthreads();

    // ---- multiply + store (smem read -> STG, fire-and-forget) ----
    #pragma unroll
    for (int i = 0; i < 2; i++) {
        const int c = w + 8 * i;
        const float4* srow = (const float4*)(sx + c * HWN);
        float4*       orow = (float4*)(ot + c * HWN);
        #pragma unroll
        for (int k = 0; k < 7; k++) {
            const int j = lane + 32 * k;
            if (j < HW4) {
                float4 v  = srow[j];
                float4 gt = s_s4[j];
                v.x *= gt.x; v.y *= gt.y; v.z *= gt.z; v.w *= gt.w;
                orow[j] = v;
            }
        }
    }
}

extern "C" void kernel_launch(void* const* d_in, const int* in_sizes, int n_in,
                              void* d_out, int out_size)
{
    const float* x  = (const float*)d_in[0];
    const float* wt = (const float*)d_in[1];
    const float* bs = (const float*)d_in[2];
    float* out = (float*)d_out;

    cudaFuncSetAttribute(simam_cluster4_kernel,
                         cudaFuncAttributeMaxDynamicSharedMemorySize, SMEM_BYTES);
    simam_cluster4_kernel<<<NCTA, NTHR, SMEM_BYTES>>>(x, wt, bs, out);
}